// round 2
// baseline (speedup 1.0000x reference)
#include <cuda_runtime.h>
#include <cstddef>

constexpr int NN   = 10000;
constexpr int EE   = 320000;
constexpr int DIN  = 512;
constexpr int DOUT = 256;

// Scratch (no allocations allowed) — __device__ globals.
__device__ float g_h[(size_t)NN * DOUT];
__device__ float g_agg[(size_t)NN * DOUT];
__device__ float g_deg[NN];
__device__ float g_invdeg[NN];
__device__ int   g_src[EE];
__device__ int   g_dst[EE];
__device__ int   g_is64;

// ---------------------------------------------------------------------------
// Edge-index dtype detection: treat raw buffer as int32 words. If the data is
// int64 (node ids < 2^31), every odd word of the first 1024 entries is 0.
// If the data is int32, odd words are random node ids (not all zero).
// ---------------------------------------------------------------------------
__global__ void detect_kernel(const int* __restrict__ raw) {
    int nz = 0;
    for (int i = threadIdx.x; i < 1024; i += blockDim.x)
        nz |= (raw[2 * i + 1] != 0);
    nz = __syncthreads_or(nz);
    if (threadIdx.x == 0) g_is64 = nz ? 0 : 1;
}

// Decode edge_index into flat int32 src/dst (handles both dtypes).
__global__ void decode_kernel(const int* __restrict__ raw,
                              int* __restrict__ src, int* __restrict__ dst) {
    int e = blockIdx.x * blockDim.x + threadIdx.x;
    if (e >= EE) return;
    if (g_is64) {                      // little-endian: low word at 2*idx
        src[e] = raw[2 * e];
        dst[e] = raw[2 * (EE + e)];
    } else {
        src[e] = raw[e];
        dst[e] = raw[EE + e];
    }
}

// ---------------------------------------------------------------------------
// Degree (computed once; same graph for both conv layers).
// ---------------------------------------------------------------------------
__global__ void deg_kernel(const int* __restrict__ dst, float* __restrict__ deg) {
    int e = blockIdx.x * blockDim.x + threadIdx.x;
    if (e < EE) atomicAdd(&deg[dst[e]], 1.0f);
}

__global__ void invdeg_kernel(const float* __restrict__ deg, float* __restrict__ inv) {
    int i = blockIdx.x * blockDim.x + threadIdx.x;
    if (i < NN) inv[i] = 1.0f / fmaxf(deg[i], 1.0f);
}

// ---------------------------------------------------------------------------
// Edge scatter: agg[dst] += h[src].  64 threads cooperate per edge, one
// float4 chunk each. Within a warp all lanes share one edge -> uniform index
// loads (broadcast) and a 512B contiguous gather/scatter. Scatter uses
// red.global.add.v4.f32 (sm_90+): 4x fewer atomic ops than scalar atomicAdd.
// Tables are ~10 MB -> L2-resident; this kernel is LTS-bound by design.
// ---------------------------------------------------------------------------
__global__ void scatter_kernel(const float* __restrict__ h,
                               const int* __restrict__ srcv,
                               const int* __restrict__ dstv,
                               float* __restrict__ agg) {
    int t = blockIdx.x * blockDim.x + threadIdx.x;   // < EE*64 = 20.48M
    int e = t >> 6;
    if (e >= EE) return;
    int c = t & 63;
    int src = srcv[e];
    int dst = dstv[e];
    float4 v = *reinterpret_cast<const float4*>(h + (size_t)src * DOUT + c * 4);
    float* addr = agg + (size_t)dst * DOUT + c * 4;
    asm volatile("red.global.add.v4.f32 [%0], {%1, %2, %3, %4};"
                 :: "l"(addr), "f"(v.x), "f"(v.y), "f"(v.z), "f"(v.w)
                 : "memory");
}

// ---------------------------------------------------------------------------
// Fused dual-GEMM: C = op( A1*scale1 @ W1  +  A2 @ W2  + bias )  [+ res]
//   op = relu if RELU.  A2/W2 pass skipped when K2 == 0.
//   scale1 (per-row, 1/deg) folds the mean into the A-tile load.
// BM=BN=64, BK=16, 256 threads, 4x4 micro-tile per thread. fp32.
// ---------------------------------------------------------------------------
template<bool RELU, bool RES>
__global__ void gemm_fused(const float* __restrict__ A1, const float* __restrict__ W1, int K1,
                           const float* __restrict__ scale1,
                           const float* __restrict__ A2, const float* __restrict__ W2, int K2,
                           const float* __restrict__ bias, const float* __restrict__ res,
                           float* __restrict__ C, int M) {
    __shared__ float As[16][65];   // padded to dodge store conflicts
    __shared__ float Ws[16][64];

    int tid = threadIdx.x;
    int tx = tid & 15;       // 0..15 (col group)
    int ty = tid >> 4;       // 0..15 (row group)
    int row0 = blockIdx.y * 64;
    int col0 = blockIdx.x * 64;

    float acc[4][4];
#pragma unroll
    for (int i = 0; i < 4; i++)
#pragma unroll
        for (int j = 0; j < 4; j++) acc[i][j] = 0.f;

    int lr = tid >> 2;          // A-tile row   0..63
    int lk = (tid & 3) * 4;     // A-tile kcol  0,4,8,12
    int wr = tid >> 4;          // W-tile row   0..15
    int wc = (tid & 15) * 4;    // W-tile col

#pragma unroll 1
    for (int pass = 0; pass < 2; pass++) {
        const float* A  = pass ? A2 : A1;
        const float* W  = pass ? W2 : W1;
        const float* sc = pass ? nullptr : scale1;
        int K = pass ? K2 : K1;
        if (K == 0) continue;

        for (int k0 = 0; k0 < K; k0 += 16) {
            // --- load A tile (64x16), row-scaled ---
            int grow = row0 + lr;
            float4 a = make_float4(0.f, 0.f, 0.f, 0.f);
            float s = 1.0f;
            if (grow < M) {
                a = *reinterpret_cast<const float4*>(A + (size_t)grow * K + k0 + lk);
                if (sc) s = sc[grow];
            }
            As[lk + 0][lr] = a.x * s;
            As[lk + 1][lr] = a.y * s;
            As[lk + 2][lr] = a.z * s;
            As[lk + 3][lr] = a.w * s;
            // --- load W tile (16x64) ---
            float4 w = *reinterpret_cast<const float4*>(W + (size_t)(k0 + wr) * DOUT + col0 + wc);
            *reinterpret_cast<float4*>(&Ws[wr][wc]) = w;
            __syncthreads();

#pragma unroll
            for (int kk = 0; kk < 16; kk++) {
                float a0 = As[kk][ty * 4 + 0];
                float a1 = As[kk][ty * 4 + 1];
                float a2 = As[kk][ty * 4 + 2];
                float a3 = As[kk][ty * 4 + 3];
                float4 b = *reinterpret_cast<const float4*>(&Ws[kk][tx * 4]);
                acc[0][0] += a0 * b.x; acc[0][1] += a0 * b.y; acc[0][2] += a0 * b.z; acc[0][3] += a0 * b.w;
                acc[1][0] += a1 * b.x; acc[1][1] += a1 * b.y; acc[1][2] += a1 * b.z; acc[1][3] += a1 * b.w;
                acc[2][0] += a2 * b.x; acc[2][1] += a2 * b.y; acc[2][2] += a2 * b.z; acc[2][3] += a2 * b.w;
                acc[3][0] += a3 * b.x; acc[3][1] += a3 * b.y; acc[3][2] += a3 * b.z; acc[3][3] += a3 * b.w;
            }
            __syncthreads();
        }
    }

    // --- epilogue: +bias, relu, +residual ---
#pragma unroll
    for (int i = 0; i < 4; i++) {
        int row = row0 + ty * 4 + i;
        if (row < M) {
#pragma unroll
            for (int j = 0; j < 4; j++) {
                int col = col0 + tx * 4 + j;
                float v = acc[i][j] + bias[col];
                if (RELU) v = fmaxf(v, 0.f);
                if (RES)  v += res[(size_t)row * DOUT + col];
                C[(size_t)row * DOUT + col] = v;
            }
        }
    }
}

// ---------------------------------------------------------------------------
// Launch: decode edges ; h = x@W0+b0 ; deg/invdeg (once) ;
//         conv1: scatter(h) -> out1 = relu(mean@Wl1+bl1 + h@Wr1) + h
//         conv2: scatter(out1) -> out2 = mean@Wl2+bl2 + out1@Wr2 + out1
// Output = concat(out1, out2), each [10000, 256] fp32.
// ---------------------------------------------------------------------------
extern "C" void kernel_launch(void* const* d_in, const int* in_sizes, int n_in,
                              void* d_out, int out_size) {
    const float* x   = (const float*)d_in[0];
    const int*   ei  = (const int*)d_in[1];     // raw words; dtype detected on-device
    const float* W0  = (const float*)d_in[2];
    const float* b0  = (const float*)d_in[3];
    const float* Wl1 = (const float*)d_in[4];
    const float* bl1 = (const float*)d_in[5];
    const float* Wr1 = (const float*)d_in[6];
    const float* Wl2 = (const float*)d_in[7];
    const float* bl2 = (const float*)d_in[8];
    const float* Wr2 = (const float*)d_in[9];

    float* out1 = (float*)d_out;
    float* out2 = out1 + (size_t)NN * DOUT;

    float *h, *agg, *deg, *invdeg;
    int *src, *dst;
    cudaGetSymbolAddress((void**)&h,      g_h);
    cudaGetSymbolAddress((void**)&agg,    g_agg);
    cudaGetSymbolAddress((void**)&deg,    g_deg);
    cudaGetSymbolAddress((void**)&invdeg, g_invdeg);
    cudaGetSymbolAddress((void**)&src,    g_src);
    cudaGetSymbolAddress((void**)&dst,    g_dst);

    dim3 ggrid(DOUT / 64, (NN + 63) / 64);       // (4, 157)
    const int scatter_blocks = (EE * 64) / 256;  // 80000 exact

    // edge decode (dtype-robust)
    detect_kernel<<<1, 256>>>(ei);
    decode_kernel<<<(EE + 255) / 256, 256>>>(ei, src, dst);

    // h = x @ W0 + b0
    gemm_fused<false, false><<<ggrid, 256>>>(x, W0, DIN, nullptr,
                                             nullptr, nullptr, 0,
                                             b0, nullptr, h, NN);

    // degree (once; same graph for both convs)
    cudaMemsetAsync(deg, 0, NN * sizeof(float));
    deg_kernel<<<(EE + 255) / 256, 256>>>(dst, deg);
    invdeg_kernel<<<(NN + 255) / 256, 256>>>(deg, invdeg);

    // conv1
    cudaMemsetAsync(agg, 0, (size_t)NN * DOUT * sizeof(float));
    scatter_kernel<<<scatter_blocks, 256>>>(h, src, dst, agg);
    gemm_fused<true, true><<<ggrid, 256>>>(agg, Wl1, DOUT, invdeg,
                                           h, Wr1, DOUT,
                                           bl1, h, out1, NN);

    // conv2
    cudaMemsetAsync(agg, 0, (size_t)NN * DOUT * sizeof(float));
    scatter_kernel<<<scatter_blocks, 256>>>(out1, src, dst, agg);
    gemm_fused<false, true><<<ggrid, 256>>>(agg, Wl2, DOUT, invdeg,
                                            out1, Wr2, DOUT,
                                            bl2, out1, out2, NN);
}